// round 3
// baseline (speedup 1.0000x reference)
#include <cuda_runtime.h>

#define NN    4096
#define BB    256
#define VOC   200
#define TT    128
#define GRID  296
#define THR   256

// ---------------- scratch (device globals; no allocation) ----------------
static __device__ float4 g_h4[(size_t)NN * 8 * BB];      // node states [node][q][batch] float4
static __device__ float4 g_part4[64 * 8 * BB];           // root partial sums
static __device__ float g_Wl[32 * 32];
static __device__ float g_bl[32];
static __device__ float g_Pa[VOC * 32];
static __device__ float g_Pb[VOC * 32];
static __device__ float g_La[VOC * 32];
static __device__ float g_Lb[VOC * 32];
static __device__ float g_F[BB * 32];
static __device__ float g_Lt[(size_t)BB * TT * 32];
static __device__ float g_v[32];
static __device__ float g_s;
static __device__ int   g_cnt[NN];
static __device__ int   g_cur[NN];
static __device__ int   g_off[NN + 1];
static __device__ int   g_child[NN];
static __device__ int   g_lvcnt[8];
static __device__ int   g_lvnodes[5 * NN];
static __device__ int   g_tA[NN * BB];
static __device__ int   g_tB[NN * BB];
static __device__ unsigned g_barctr;

// ---------------- f32x2 helpers ----------------
__device__ __forceinline__ unsigned long long pack2(float lo, float hi) {
    unsigned long long r;
    asm("mov.b64 %0, {%1, %2};" : "=l"(r) : "r"(__float_as_uint(lo)), "r"(__float_as_uint(hi)));
    return r;
}
__device__ __forceinline__ void unpack2(unsigned long long v, float& lo, float& hi) {
    unsigned int a, b;
    asm("mov.b64 {%0, %1}, %2;" : "=r"(a), "=r"(b) : "l"(v));
    lo = __uint_as_float(a);
    hi = __uint_as_float(b);
}
__device__ __forceinline__ void fma2(unsigned long long& d, unsigned long long a, unsigned long long b) {
    asm("fma.rn.f32x2 %0, %1, %2, %0;" : "+l"(d) : "l"(a), "l"(b));
}

// ---------------- global barrier (persistent kernel) ----------------
__device__ __forceinline__ void gbar(unsigned target) {
    __syncthreads();
    if (threadIdx.x == 0) {
        __threadfence();
        atomicAdd(&g_barctr, 1u);
        unsigned v;
        do {
            asm volatile("ld.acquire.gpu.u32 %0, [%1];" : "=r"(v) : "l"(&g_barctr) : "memory");
        } while (v < target);
    }
    __syncthreads();
}

// ---------------- setup: fuse + tables + zeroing (1 block) ----------------
__global__ void k_setup(const float* lw1, const float* lb1, const float* lw2, const float* lb2,
                        const float* fw1, const float* fb1, const float* fw2, const float* fb2,
                        const float* tw, const float* tb,
                        const float* emb, const float* node_w, const float* node_b) {
    __shared__ float u[32];
    int t = threadIdx.x;
    for (int i = t; i < NN; i += 1024) { g_cnt[i] = 0; g_cur[i] = 0; }
    if (t < 8) g_lvcnt[t] = 0;
    if (t == 0) g_barctr = 0u;
    int i = t >> 5, j = t & 31;
    float s = 0.f;
    for (int k = 0; k < 32; k++) s += lw1[i * 32 + k] * lw2[k * 32 + j];
    g_Wl[t] = s;
    if (t < 32) {
        float bsum = lb2[t];
        for (int k = 0; k < 32; k++) bsum += lb1[k] * lw2[k * 32 + t];
        g_bl[t] = bsum;
        float uu = 0.f;
        for (int q = 0; q < 32; q++) uu += fw2[t * 32 + q] * tw[q];
        u[t] = uu;
    }
    __syncthreads();
    if (t < 32) {
        float vv = 0.f;
        for (int k = 0; k < 32; k++) vv += fw1[t * 32 + k] * u[k];
        g_v[t] = vv;
    }
    if (t == 0) {
        float ss = tb[0];
        for (int k = 0; k < 32; k++) ss += fb1[k] * u[k];
        for (int q = 0; q < 32; q++) ss += fb2[q] * tw[q];
        g_s = ss;
    }
    __syncthreads();
    // tables (6400 outputs)
    for (int idx = t; idx < VOC * 32; idx += 1024) {
        int v = idx >> 5, jj = idx & 31;
        float la = g_bl[jj], lb = 0.f, pa = node_b[jj], pb = 0.f;
        for (int e = 0; e < 16; e++) {
            float ev = emb[v * 16 + e];
            la += ev * g_Wl[e * 32 + jj];
            lb += ev * g_Wl[(16 + e) * 32 + jj];
            pa += ev * node_w[e * 32 + jj];
            pb += ev * node_w[(16 + e) * 32 + jj];
        }
        g_La[idx] = la;
        g_Lb[idx] = lb;
        g_Pa[idx] = pa;
        g_Pb[idx] = pb;
    }
}

// ---------------- the mega kernel ----------------
__global__ void __launch_bounds__(THR, 2) k_mega(
    const int* __restrict__ kind, const int* __restrict__ height,
    const int* __restrict__ parent,
    const int* __restrict__ tok_a, const int* __restrict__ tok_b,
    const int* __restrict__ ptr_time,
    const float* __restrict__ first_notes, const float* __restrict__ lstm,
    const float* __restrict__ node_w,
    const float* __restrict__ ptr_w, const float* __restrict__ ptr_b,
    float* __restrict__ out)
{
    extern __shared__ float dsm[];
    float* Pash = dsm;            // 200*36 = 7200
    float* Pbsh = dsm + 7200;     // 7200
    float* scr  = dsm + 14400;    // 6528 floats (Lt scratch)
    __shared__ __align__(16) ulonglong2 Wsh[256];
    __shared__ int tileb[32][33];
    __shared__ int sA[256];

    const int t   = threadIdx.x;
    const int bid = blockIdx.x;

    // prologue: load tables + weight into smem (all blocks)
    for (int i = t; i < VOC * 32; i += THR) {
        int v = i >> 5, j = i & 31;
        Pash[v * 36 + j] = g_Pa[i];
        Pbsh[v * 36 + j] = g_Pb[i];
    }
    Wsh[t] = ((const ulonglong2*)(node_w + 1024))[t];
    __syncthreads();

    // ================= Phase A: transpose | Lt | csr-count | F =================
    if (bid < 192) {
        // transpose tok_a, tok_b: 2048 tiles of 32x32
        for (int ti = bid; ti < 2048; ti += 192) {
            int arr  = ti >> 10;
            int tile = ti & 1023;
            int pt = tile >> 3, bt = tile & 7;
            const int* src = arr ? tok_b : tok_a;
            int* dst = arr ? g_tB : g_tA;
            int lane = t & 31, r0 = t >> 5;
            for (int r = r0; r < 32; r += 8)
                tileb[r][lane] = src[(size_t)(bt * 32 + r) * NN + pt * 32 + lane];
            __syncthreads();
            for (int r = r0; r < 32; r += 8)
                dst[(size_t)(pt * 32 + r) * BB + bt * 32 + lane] = tileb[lane][r];
            __syncthreads();
        }
    } else if (bid < 288) {
        // Lt: [32768, 64] @ [64, 32] in groups of 64 rows
        float* lssh = scr;          // 64*68
        float* pwT  = scr + 4352;   // 32*68
        for (int i = t; i < 2048; i += THR)
            pwT[(i & 31) * 68 + (i >> 5)] = ptr_w[2048 + i];
        for (int g = bid - 192; g < 512; g += 96) {
            __syncthreads();
            size_t base = (size_t)g * 4096;
            for (int i = t; i < 4096; i += THR)
                lssh[(i >> 6) * 68 + (i & 63)] = lstm[base + i];
            __syncthreads();
            int w = t >> 5, j = t & 31;
            float s[8];
            #pragma unroll
            for (int r = 0; r < 8; r++) s[r] = 0.f;
            #pragma unroll
            for (int k4 = 0; k4 < 64; k4 += 4) {
                float4 wv = *(const float4*)(pwT + j * 68 + k4);
                #pragma unroll
                for (int r = 0; r < 8; r++) {
                    float4 lv = *(const float4*)(lssh + (w * 8 + r) * 68 + k4);
                    s[r] += lv.x * wv.x + lv.y * wv.y + lv.z * wv.z + lv.w * wv.w;
                }
            }
            int row0 = g * 64 + w * 8;
            #pragma unroll
            for (int r = 0; r < 8; r++)
                g_Lt[(size_t)(row0 + r) * 32 + j] = s[r];
        }
    } else if (bid < 295) {
        for (int c = (bid - 288) * THR + t; c < NN; c += 7 * THR)
            if (c >= 1) atomicAdd(&g_cnt[parent[c]], 1);
    } else {
        // F: first_notes @ ptr_w_top + ptr_b
        for (int idx = t; idx < BB * 32; idx += THR) {
            int b = idx >> 5, j = idx & 31;
            float s = ptr_b[j];
            for (int k = 0; k < 64; k++) s += first_notes[b * 64 + k] * ptr_w[k * 32 + j];
            g_F[idx] = s;
        }
    }
    gbar(GRID * 1);

    // ================= Phase B: scan (block 0) | leaf (blocks 1..295) =========
    if (bid == 0) {
        int base = t * 16;
        int loc[16];
        int run = 0;
        #pragma unroll
        for (int r = 0; r < 16; r++) { loc[r] = run; run += g_cnt[base + r]; }
        sA[t] = run;
        __syncthreads();
        for (int off = 1; off < 256; off <<= 1) {
            int v = (t >= off) ? sA[t - off] : 0;
            __syncthreads();
            sA[t] += v;
            __syncthreads();
        }
        int excl = sA[t] - run;
        #pragma unroll
        for (int r = 0; r < 16; r++) g_off[base + r] = excl + loc[r];
        if (t == 255) g_off[NN] = sA[255];
    } else {
        int b = t;
        for (int p = bid - 1; p < NN; p += GRID - 1) {
            if (height[p] != 0) continue;
            int kd = kind[p];
            float4 r[8];
            if (kd == 0) {
                int ta = g_tA[p * BB + b];
                int tb = g_tB[p * BB + b];
                const float4* A  = (const float4*)(g_La + ta * 32);
                const float4* Bv = (const float4*)(g_Lb + tb * 32);
                #pragma unroll
                for (int q = 0; q < 8; q++) {
                    float4 x = A[q], y = Bv[q];
                    r[q] = make_float4(x.x + y.x, x.y + y.y, x.z + y.z, x.w + y.w);
                }
            } else {
                int tm = ptr_time[(size_t)b * NN + p];
                const float4* A  = (const float4*)(g_F + b * 32);
                const float4* Bv = (const float4*)(g_Lt + ((size_t)b * TT + tm) * 32);
                #pragma unroll
                for (int q = 0; q < 8; q++) {
                    float4 x = A[q], y = Bv[q];
                    r[q] = make_float4(x.x + y.x, x.y + y.y, x.z + y.z, x.w + y.w);
                }
            }
            float4* dst = g_h4 + (size_t)p * 8 * BB + b;
            #pragma unroll
            for (int q = 0; q < 8; q++) dst[q * BB] = r[q];
        }
    }
    gbar(GRID * 2);

    // ================= Phase C: csr fill + level lists =========================
    {
        int c = bid * THR + t;
        if (c >= 1 && c < NN) {
            int p = parent[c];
            int pos = atomicAdd(&g_cur[p], 1);
            g_child[g_off[p] + pos] = c;
        }
        if (c < NN) {
            int h = height[c];
            if (h >= 1 && h <= 5) {
                int i = atomicAdd(&g_lvcnt[h], 1);
                g_lvnodes[(h - 1) * NN + i] = c;
            }
        }
    }
    gbar(GRID * 3);

    // ================= Levels 1..5 =============================================
    for (int lvl = 1; lvl <= 5; lvl++) {
        int cnt = g_lvcnt[lvl];
        int b = t;
        for (int ni = bid; ni < cnt; ni += GRID) {
            int p = g_lvnodes[(lvl - 1) * NN + ni];
            float acc[32];
            #pragma unroll
            for (int i = 0; i < 32; i++) acc[i] = 0.f;
            int cs = g_off[p], ce = g_off[p + 1];
            for (int ci = cs; ci < ce; ci++) {
                int c = g_child[ci];
                const float4* src = g_h4 + (size_t)c * 8 * BB + b;
                #pragma unroll
                for (int q = 0; q < 8; q++) {
                    float4 v = src[q * BB];
                    acc[4 * q] += v.x; acc[4 * q + 1] += v.y;
                    acc[4 * q + 2] += v.z; acc[4 * q + 3] += v.w;
                }
            }
            int ta = g_tA[p * BB + b];
            int tb = g_tB[p * BB + b];
            const float4* pa = (const float4*)(Pash + ta * 36);
            const float4* pb = (const float4*)(Pbsh + tb * 36);
            unsigned long long o2[16];
            #pragma unroll
            for (int q = 0; q < 8; q++) {
                float4 x = pa[q], y = pb[q];
                o2[2 * q]     = pack2(x.x + y.x, x.y + y.y);
                o2[2 * q + 1] = pack2(x.z + y.z, x.w + y.w);
            }
            #pragma unroll
            for (int k = 0; k < 32; k++) {
                unsigned long long a2 = pack2(acc[k], acc[k]);
                #pragma unroll
                for (int j2 = 0; j2 < 8; j2++) {
                    ulonglong2 w = Wsh[k * 8 + j2];
                    fma2(o2[2 * j2], a2, w.x);
                    fma2(o2[2 * j2 + 1], a2, w.y);
                }
            }
            float4* dst = g_h4 + (size_t)p * 8 * BB + b;
            #pragma unroll
            for (int q = 0; q < 8; q++) {
                float l0, h0, l1, h1;
                unpack2(o2[2 * q], l0, h0);
                unpack2(o2[2 * q + 1], l1, h1);
                dst[q * BB] = make_float4(fmaxf(l0, 0.f), fmaxf(h0, 0.f),
                                          fmaxf(l1, 0.f), fmaxf(h1, 0.f));
            }
        }
        gbar(GRID * (3 + lvl));
    }

    // ================= Root reduction F1 (64 blocks) ===========================
    if (bid < 64) {
        int b = t;
        float acc[32];
        #pragma unroll
        for (int i = 0; i < 32; i++) acc[i] = 0.f;
        int cs = g_off[0], ce = g_off[1];
        for (int ci = cs + bid; ci < ce; ci += 64) {
            int c = g_child[ci];
            const float4* src = g_h4 + (size_t)c * 8 * BB + b;
            #pragma unroll
            for (int q = 0; q < 8; q++) {
                float4 v = src[q * BB];
                acc[4 * q] += v.x; acc[4 * q + 1] += v.y;
                acc[4 * q + 2] += v.z; acc[4 * q + 3] += v.w;
            }
        }
        float4* dst = g_part4 + (size_t)bid * 8 * BB + b;
        #pragma unroll
        for (int q = 0; q < 8; q++)
            dst[q * BB] = make_float4(acc[4 * q], acc[4 * q + 1], acc[4 * q + 2], acc[4 * q + 3]);
    }
    gbar(GRID * 9);

    // ================= F2: 64 -> 8 partials (8 blocks) =========================
    if (bid < 8) {
        int b = t;
        float4 acc[8];
        #pragma unroll
        for (int q = 0; q < 8; q++) acc[q] = make_float4(0.f, 0.f, 0.f, 0.f);
        for (int pr = bid; pr < 64; pr += 8) {
            const float4* src = g_part4 + (size_t)pr * 8 * BB + b;
            #pragma unroll
            for (int q = 0; q < 8; q++) {
                float4 v = src[q * BB];
                acc[q].x += v.x; acc[q].y += v.y; acc[q].z += v.z; acc[q].w += v.w;
            }
        }
        float4* dst = g_part4 + (size_t)bid * 8 * BB + b;
        #pragma unroll
        for (int q = 0; q < 8; q++) dst[q * BB] = acc[q];
    }
    gbar(GRID * 10);

    // ================= F3: finish (block 0) ====================================
    if (bid == 0) {
        int b = t;
        float cs[32];
        #pragma unroll
        for (int i = 0; i < 32; i++) cs[i] = 0.f;
        for (int pr = 0; pr < 8; pr++) {
            const float4* src = g_part4 + (size_t)pr * 8 * BB + b;
            #pragma unroll
            for (int q = 0; q < 8; q++) {
                float4 v = src[q * BB];
                cs[4 * q] += v.x; cs[4 * q + 1] += v.y;
                cs[4 * q + 2] += v.z; cs[4 * q + 3] += v.w;
            }
        }
        int ta = g_tA[b];
        int tb = g_tB[b];
        float o[32];
        #pragma unroll
        for (int j = 0; j < 32; j++) o[j] = Pash[ta * 36 + j] + Pbsh[tb * 36 + j];
        for (int k = 0; k < 32; k++) {
            float a = cs[k];
            #pragma unroll
            for (int j = 0; j < 32; j++) o[j] += a * node_w[(32 + k) * 32 + j];
        }
        float val = 0.f;
        #pragma unroll
        for (int j = 0; j < 32; j++) val += fmaxf(o[j], 0.f) * g_v[j];
        out[b] = val + g_s;
    }
}

// ---------------- launch ----------------
extern "C" void kernel_launch(void* const* d_in, const int* in_sizes, int n_in,
                              void* d_out, int out_size) {
    const int*   kind        = (const int*)d_in[0];
    const int*   height      = (const int*)d_in[1];
    const int*   parent      = (const int*)d_in[2];
    const int*   tok_a       = (const int*)d_in[3];
    const int*   tok_b       = (const int*)d_in[4];
    const int*   ptr_time    = (const int*)d_in[5];
    const float* first_notes = (const float*)d_in[6];
    const float* lstm_out    = (const float*)d_in[7];
    const float* embedding   = (const float*)d_in[8];
    const float* leaf_w1     = (const float*)d_in[9];
    const float* leaf_b1     = (const float*)d_in[10];
    const float* leaf_w2     = (const float*)d_in[11];
    const float* leaf_b2     = (const float*)d_in[12];
    const float* node_w      = (const float*)d_in[13];
    const float* node_b      = (const float*)d_in[14];
    const float* ptr_w       = (const float*)d_in[15];
    const float* ptr_b       = (const float*)d_in[16];
    const float* ff_w1       = (const float*)d_in[17];
    const float* ff_b1       = (const float*)d_in[18];
    const float* ff_w2       = (const float*)d_in[19];
    const float* ff_b2       = (const float*)d_in[20];
    const float* tail_w      = (const float*)d_in[21];
    const float* tail_b      = (const float*)d_in[22];
    float* out = (float*)d_out;

    static int smem_set = 0;
    if (!smem_set) {
        cudaFuncSetAttribute(k_mega, cudaFuncAttributeMaxDynamicSharedMemorySize, 83712);
        smem_set = 1;
    }

    k_setup<<<1, 1024>>>(leaf_w1, leaf_b1, leaf_w2, leaf_b2,
                         ff_w1, ff_b1, ff_w2, ff_b2, tail_w, tail_b,
                         embedding, node_w, node_b);
    k_mega<<<GRID, THR, 83712>>>(kind, height, parent, tok_a, tok_b, ptr_time,
                                 first_notes, lstm_out, node_w, ptr_w, ptr_b, out);
}